// round 4
// baseline (speedup 1.0000x reference)
#include <cuda_runtime.h>
#include <cuda_bf16.h>
#include <math.h>
#include <stdint.h>

#define N_NODES   100000
#define N_EDGES   1600000
#define N_GRAPHS  256
#define IN_DIM    64
#define HID       128
#define RELU_COEF 0.05f

typedef unsigned long long ull;

// ---------------- scratch (no allocation allowed) ----------------
__device__ float g_agg1[(size_t)N_NODES * IN_DIM];
__device__ float g_agg2[(size_t)N_NODES * HID];
__device__ float g_h1  [(size_t)N_NODES * HID];
__device__ float g_h2  [(size_t)N_NODES * HID];
__device__ float g_pool[N_GRAPHS * HID];
__device__ int   g_deg   [N_NODES];
__device__ int   g_rowptr[N_NODES];
__device__ int   g_fill  [N_NODES];
__device__ int2  g_epak  [N_EDGES];
__device__ int   g_blksum[512];

__device__ __forceinline__ float lrelu(float v) {
    return v > 0.f ? v : RELU_COEF * v;
}

// ---------------- mma.sync / ldmatrix helpers (plain PTX, sm_80+) --------
__device__ __forceinline__ uint32_t smem_u32(const void* p) {
    uint32_t a;
    asm("{ .reg .u64 t; cvta.to.shared.u64 t, %1; cvt.u32.u64 %0, t; }" : "=r"(a) : "l"(p));
    return a;
}
#define LDSM_X4(r0, r1, r2, r3, addr) \
    asm volatile("ldmatrix.sync.aligned.m8n8.x4.shared.b16 {%0,%1,%2,%3}, [%4];" \
                 : "=r"(r0), "=r"(r1), "=r"(r2), "=r"(r3) : "r"(addr))
#define LDSM_X2(r0, r1, addr) \
    asm volatile("ldmatrix.sync.aligned.m8n8.x2.shared.b16 {%0,%1}, [%2];" \
                 : "=r"(r0), "=r"(r1) : "r"(addr))
#define MMA_BF16(c, a, b0, b1) \
    asm volatile("mma.sync.aligned.m16n8k16.row.col.f32.bf16.bf16.f32 " \
                 "{%0,%1,%2,%3}, {%4,%5,%6,%7}, {%8,%9}, {%0,%1,%2,%3};" \
                 : "+f"((c)[0]), "+f"((c)[1]), "+f"((c)[2]), "+f"((c)[3]) \
                 : "r"((a)[0]), "r"((a)[1]), "r"((a)[2]), "r"((a)[3]), \
                   "r"(b0), "r"(b1))

__device__ __forceinline__ void bf16_split(float v, unsigned short& h, unsigned short& l) {
    __nv_bfloat16 hb = __float2bfloat16(v);
    __nv_bfloat16 lb = __float2bfloat16(v - __bfloat162float(hb));
    h = __bfloat16_as_ushort(hb);
    l = __bfloat16_as_ushort(lb);
}

#define PITCH 72   // bf16 elements per smem tile row (64 + 8 pad -> conflict-free ldmatrix)

// ---------------- small utility kernels ----------------
__global__ void zero_f4_kernel(float4* p, int n4) {
    int i = blockIdx.x * blockDim.x + threadIdx.x;
    if (i < n4) p[i] = make_float4(0.f, 0.f, 0.f, 0.f);
}
__global__ void zero_int_kernel(int* p, int n) {
    int i = blockIdx.x * blockDim.x + threadIdx.x;
    if (i < n) p[i] = 0;
}

// ---------------- CSR build ----------------
__global__ void hist_kernel(const int* __restrict__ dst, int* __restrict__ deg) {
    int e = blockIdx.x * blockDim.x + threadIdx.x;
    if (e < N_EDGES) atomicAdd(&deg[dst[e]], 1);
}
__global__ void scan1_kernel(const int* __restrict__ deg, int* __restrict__ rowptr,
                             int* __restrict__ blksum) {
    __shared__ int s[256];
    int i = blockIdx.x * 256 + threadIdx.x;
    int v = (i < N_NODES) ? deg[i] : 0;
    s[threadIdx.x] = v;
    __syncthreads();
    for (int off = 1; off < 256; off <<= 1) {
        int t = 0;
        if (threadIdx.x >= off) t = s[threadIdx.x - off];
        __syncthreads();
        s[threadIdx.x] += t;
        __syncthreads();
    }
    if (i < N_NODES) rowptr[i] = s[threadIdx.x] - v;
    if (threadIdx.x == 255) blksum[blockIdx.x] = s[255];
}
__global__ void scan2_kernel(int* blksum, int nblk) {
    __shared__ int s[512];
    int t = threadIdx.x;
    int v = (t < nblk) ? blksum[t] : 0;
    s[t] = v;
    __syncthreads();
    for (int off = 1; off < 512; off <<= 1) {
        int u = (t >= off) ? s[t - off] : 0;
        __syncthreads();
        s[t] += u;
        __syncthreads();
    }
    if (t < nblk) blksum[t] = s[t] - v;
}
__global__ void scan3_kernel(int* __restrict__ rowptr, int* __restrict__ fill,
                             const int* __restrict__ blksum) {
    int i = blockIdx.x * 256 + threadIdx.x;
    if (i < N_NODES) {
        int r = rowptr[i] + blksum[blockIdx.x];
        rowptr[i] = r;
        fill[i] = r;
    }
}
__global__ void fill_kernel(const int* __restrict__ src, const int* __restrict__ dst,
                            const float* __restrict__ w, int* __restrict__ fill,
                            int2* __restrict__ epak) {
    int e = blockIdx.x * blockDim.x + threadIdx.x;
    if (e < N_EDGES) {
        int pos = atomicAdd(&fill[dst[e]], 1);
        epak[pos] = make_int2(src[e], __float_as_int(w[e]));
    }
}

// ---------------- gather aggregation: warp per node ----------------
template<int D>
__global__ void __launch_bounds__(256)
gather_kernel(const float* __restrict__ x, const int* __restrict__ rowptr,
              const int* __restrict__ deg, const int2* __restrict__ epak,
              float* __restrict__ agg)
{
    int warp = (blockIdx.x * blockDim.x + threadIdx.x) >> 5;
    int lane = threadIdx.x & 31;
    if (warp >= N_NODES) return;
    int start = rowptr[warp];
    int d = deg[warp];
    if (D == 128) {
        float4 acc = make_float4(0.f, 0.f, 0.f, 0.f);
        for (int i = 0; i < d; i++) {
            int2 p = epak[start + i];
            float ww = __int_as_float(p.y);
            float4 v = *(const float4*)(x + (size_t)p.x * 128 + lane * 4);
            acc.x += ww * v.x; acc.y += ww * v.y;
            acc.z += ww * v.z; acc.w += ww * v.w;
        }
        *(float4*)(agg + (size_t)warp * 128 + lane * 4) = acc;
    } else {
        float2 acc = make_float2(0.f, 0.f);
        for (int i = 0; i < d; i++) {
            int2 p = epak[start + i];
            float ww = __int_as_float(p.y);
            float2 v = *(const float2*)(x + (size_t)p.x * 64 + lane * 2);
            acc.x += ww * v.x; acc.y += ww * v.y;
        }
        *(float2*)(agg + (size_t)warp * 64 + lane * 2) = acc;
    }
}

// ---------------- shared A-chunk loader (hi/lo bf16 planes) --------------
__device__ __forceinline__ void load_A_chunk(const float* __restrict__ S, int SD,
                                             int soff, int n0,
                                             unsigned short* AH, unsigned short* AL,
                                             int tid)
{
    // 128 rows x 64 cols; 8 float4 per thread
    for (int i = tid; i < 128 * 16; i += 256) {
        int r  = i >> 4;
        int c4 = (i & 15) * 4;
        int gn = n0 + r;
        float4 v = make_float4(0.f, 0.f, 0.f, 0.f);
        if (gn < N_NODES) v = *(const float4*)(S + (size_t)gn * SD + soff + c4);
        unsigned short h[4], l[4];
        bf16_split(v.x, h[0], l[0]); bf16_split(v.y, h[1], l[1]);
        bf16_split(v.z, h[2], l[2]); bf16_split(v.w, h[3], l[3]);
        *(uint2*)&AH[r * PITCH + c4] = *(uint2*)h;
        *(uint2*)&AL[r * PITCH + c4] = *(uint2*)l;
    }
}

// ---------------- fused dual-input linear + leaky (split-bf16 mma) -------
// out[n, 0:128] = lrelu( A1[n]@W1 + A2[n]@W2 + bias );  K1,K2 multiples of 64
template<int K1, int K2>
__global__ void __launch_bounds__(256, 1)
mma_linear_kernel(const float* __restrict__ A1, const float* __restrict__ A2,
                  const float* __restrict__ W1, const float* __restrict__ W2,
                  const float* __restrict__ bias, float* __restrict__ out)
{
    constexpr int K = K1 + K2;
    constexpr int NCH = K / 64;
    extern __shared__ char smem[];
    unsigned short* AH = (unsigned short*)(smem);
    unsigned short* AL = AH + 128 * PITCH;
    unsigned short* BH = AL + 128 * PITCH;
    unsigned short* BL = BH + 128 * PITCH;
    const uint32_t sAH = smem_u32(AH), sAL = smem_u32(AL);
    const uint32_t sBH = smem_u32(BH), sBL = smem_u32(BL);

    const int tid  = threadIdx.x;
    const int wid  = tid >> 5;
    const int lane = tid & 31;
    const int n0   = blockIdx.x * 128;
    const int mr   = (wid & 3) * 32;
    const int nb   = (wid >> 2) * 64;

    // ldmatrix per-lane address offsets
    const int arow = (lane & 7) + ((lane >> 3) & 1) * 8;
    const int acol = (lane >> 4) * 8;
    const int brow = lane & 7;
    const int bcol = ((lane >> 3) & 1) * 8;

    float c[2][8][4];
#pragma unroll
    for (int mi = 0; mi < 2; mi++)
#pragma unroll
        for (int ni = 0; ni < 8; ni++)
#pragma unroll
            for (int j = 0; j < 4; j++) c[mi][ni][j] = 0.f;

    for (int ch = 0; ch < NCH; ch++) {
        int kc = ch * 64;
        const float* S; int SD, soff;
        if (kc < K1) { S = A1; SD = K1; soff = kc; }
        else         { S = A2; SD = K2; soff = kc - K1; }
        load_A_chunk(S, SD, soff, n0, AH, AL, tid);
        // B chunk: Bt[n][k] transposed from W[kc+k][n]
        for (int i = tid; i < 64 * 32; i += 256) {
            int k  = i >> 5;
            int n4 = (i & 31) * 4;
            int gk = kc + k;
            const float* wp = (gk < K1) ? (W1 + (size_t)gk * 128 + n4)
                                        : (W2 + (size_t)(gk - K1) * 128 + n4);
            float4 v = *(const float4*)wp;
            unsigned short h[4], l[4];
            bf16_split(v.x, h[0], l[0]); bf16_split(v.y, h[1], l[1]);
            bf16_split(v.z, h[2], l[2]); bf16_split(v.w, h[3], l[3]);
#pragma unroll
            for (int j = 0; j < 4; j++) {
                BH[(n4 + j) * PITCH + k] = h[j];
                BL[(n4 + j) * PITCH + k] = l[j];
            }
        }
        __syncthreads();
#pragma unroll
        for (int ks = 0; ks < 4; ks++) {
            int k16 = ks * 16;
            uint32_t aH[2][4], aL[2][4];
#pragma unroll
            for (int mi = 0; mi < 2; mi++) {
                uint32_t off = ((mr + mi * 16 + arow) * PITCH + k16 + acol) * 2;
                LDSM_X4(aH[mi][0], aH[mi][1], aH[mi][2], aH[mi][3], sAH + off);
                LDSM_X4(aL[mi][0], aL[mi][1], aL[mi][2], aL[mi][3], sAL + off);
            }
#pragma unroll
            for (int ni = 0; ni < 8; ni++) {
                uint32_t off = ((nb + ni * 8 + brow) * PITCH + k16 + bcol) * 2;
                uint32_t bh0, bh1, bl0, bl1;
                LDSM_X2(bh0, bh1, sBH + off);
                LDSM_X2(bl0, bl1, sBL + off);
#pragma unroll
                for (int mi = 0; mi < 2; mi++) {
                    MMA_BF16(c[mi][ni], aH[mi], bh0, bh1);
                    MMA_BF16(c[mi][ni], aH[mi], bl0, bl1);
                    MMA_BF16(c[mi][ni], aL[mi], bh0, bh1);
                }
            }
        }
        __syncthreads();
    }

    // epilogue
#pragma unroll
    for (int mi = 0; mi < 2; mi++) {
        int r0 = n0 + mr + mi * 16 + (lane >> 2);
        int r1 = r0 + 8;
#pragma unroll
        for (int ni = 0; ni < 8; ni++) {
            int col = nb + ni * 8 + (lane & 3) * 2;
            float b0 = bias[col], b1 = bias[col + 1];
            if (r0 < N_NODES) {
                float2 o = make_float2(lrelu(c[mi][ni][0] + b0), lrelu(c[mi][ni][1] + b1));
                *(float2*)(out + (size_t)r0 * 128 + col) = o;
            }
            if (r1 < N_NODES) {
                float2 o = make_float2(lrelu(c[mi][ni][2] + b0), lrelu(c[mi][ni][3] + b1));
                *(float2*)(out + (size_t)r1 * 128 + col) = o;
            }
        }
    }
}

// ---------------- fused gate + pool (split-bf16 mma, N=256 paired) -------
__global__ void __launch_bounds__(256, 1)
mma_gate_kernel(const float* __restrict__ h2, const float* __restrict__ x0,
                const float* __restrict__ Wsig, const float* __restrict__ Wtanh,
                const float* __restrict__ bsig, const float* __restrict__ btanh,
                const int* __restrict__ batch, float* __restrict__ pool)
{
    constexpr int K1 = HID, K2 = IN_DIM;
    constexpr int NCH = (K1 + K2) / 64;   // 3
    extern __shared__ char smem[];
    unsigned short* AH = (unsigned short*)(smem);
    unsigned short* AL = AH + 128 * PITCH;
    unsigned short* BH = AL + 128 * PITCH;
    unsigned short* BL = BH + 256 * PITCH;
    const uint32_t sAH = smem_u32(AH), sAL = smem_u32(AL);
    const uint32_t sBH = smem_u32(BH), sBL = smem_u32(BL);

    const int tid  = threadIdx.x;
    const int wid  = tid >> 5;
    const int lane = tid & 31;
    const int n0   = blockIdx.x * 128;
    const int mr   = (wid & 3) * 32;
    const int cw   = wid >> 2;           // 0/1: sig cols cw*64.., tanh at +128

    const int arow = (lane & 7) + ((lane >> 3) & 1) * 8;
    const int acol = (lane >> 4) * 8;
    const int brow = lane & 7;
    const int bcol = ((lane >> 3) & 1) * 8;

    float c[2][16][4];                   // ni 0-7: sig; ni 8-15: tanh (same cols)
#pragma unroll
    for (int mi = 0; mi < 2; mi++)
#pragma unroll
        for (int ni = 0; ni < 16; ni++)
#pragma unroll
            for (int j = 0; j < 4; j++) c[mi][ni][j] = 0.f;

    for (int ch = 0; ch < NCH; ch++) {
        int kc = ch * 64;
        const float* S; int SD, soff;
        if (kc < K1) { S = h2; SD = K1; soff = kc; }
        else         { S = x0; SD = K2; soff = kc - K1; }
        load_A_chunk(S, SD, soff, n0, AH, AL, tid);
        // B chunk: 256 rows (0-127 sig cols, 128-255 tanh cols)
        for (int i = tid; i < 64 * 64; i += 256) {
            int k  = i >> 6;
            int n4 = (i & 63) * 4;
            int gk = kc + k;
            const float* wp = (n4 < 128) ? (Wsig  + (size_t)gk * 128 + n4)
                                         : (Wtanh + (size_t)gk * 128 + (n4 - 128));
            float4 v = *(const float4*)wp;
            unsigned short h[4], l[4];
            bf16_split(v.x, h[0], l[0]); bf16_split(v.y, h[1], l[1]);
            bf16_split(v.z, h[2], l[2]); bf16_split(v.w, h[3], l[3]);
#pragma unroll
            for (int j = 0; j < 4; j++) {
                BH[(n4 + j) * PITCH + k] = h[j];
                BL[(n4 + j) * PITCH + k] = l[j];
            }
        }
        __syncthreads();
#pragma unroll
        for (int ks = 0; ks < 4; ks++) {
            int k16 = ks * 16;
            uint32_t aH[2][4], aL[2][4];
#pragma unroll
            for (int mi = 0; mi < 2; mi++) {
                uint32_t off = ((mr + mi * 16 + arow) * PITCH + k16 + acol) * 2;
                LDSM_X4(aH[mi][0], aH[mi][1], aH[mi][2], aH[mi][3], sAH + off);
                LDSM_X4(aL[mi][0], aL[mi][1], aL[mi][2], aL[mi][3], sAL + off);
            }
#pragma unroll
            for (int ni = 0; ni < 16; ni++) {
                int nrow = (ni < 8) ? (cw * 64 + ni * 8) : (128 + cw * 64 + (ni - 8) * 8);
                uint32_t off = ((nrow + brow) * PITCH + k16 + bcol) * 2;
                uint32_t bh0, bh1, bl0, bl1;
                LDSM_X2(bh0, bh1, sBH + off);
                LDSM_X2(bl0, bl1, sBL + off);
#pragma unroll
                for (int mi = 0; mi < 2; mi++) {
                    MMA_BF16(c[mi][ni], aH[mi], bh0, bh1);
                    MMA_BF16(c[mi][ni], aH[mi], bl0, bl1);
                    MMA_BF16(c[mi][ni], aL[mi], bh0, bh1);
                }
            }
        }
        __syncthreads();
    }

    // epilogue: g = tanh(tx)*sigmoid(-sx) -> smem, then run-length pooling
    float (*g_s)[132] = (float(*)[132])smem;   // 128 x 132 floats (tiles dead)
    __syncthreads();
#pragma unroll
    for (int mi = 0; mi < 2; mi++) {
        int r0 = mr + mi * 16 + (lane >> 2);
#pragma unroll
        for (int ni = 0; ni < 8; ni++) {
            int col = cw * 64 + ni * 8 + (lane & 3) * 2;
            float bs0 = bsig[col], bs1 = bsig[col + 1];
            float bt0 = btanh[col], bt1 = btanh[col + 1];
#pragma unroll
            for (int h = 0; h < 2; h++) {       // h=0: row r0, c[0|1]; h=1: r0+8, c[2|3]
                int r = r0 + h * 8;
                float sx0 = fminf(fmaxf(c[mi][ni][2 * h + 0] + bs0, -30.f), 30.f);
                float sx1 = fminf(fmaxf(c[mi][ni][2 * h + 1] + bs1, -30.f), 30.f);
                float tx0 = c[mi][ni + 8][2 * h + 0] + bt0;
                float tx1 = c[mi][ni + 8][2 * h + 1] + bt1;
                g_s[r][col]     = tanhf(tx0) / (1.f + expf(sx0));
                g_s[r][col + 1] = tanhf(tx1) / (1.f + expf(sx1));
            }
        }
    }
    __syncthreads();

    // pooling: thread -> (col, half); rows sorted by batch -> run-length
    int col  = tid & 127;
    int half = tid >> 7;
    int curb = -1;
    float s = 0.f;
    for (int r = half * 64; r < half * 64 + 64; r++) {
        int n = n0 + r;
        if (n >= N_NODES) break;
        int b = batch[n];
        float g = g_s[r][col];
        if (b != curb) {
            if (curb >= 0) atomicAdd(pool + (size_t)curb * 128 + col, s);
            curb = b; s = g;
        } else s += g;
    }
    if (curb >= 0) atomicAdd(pool + (size_t)curb * 128 + col, s);
}

// ---------------- head MLP: one block per graph ----------------
__global__ void __launch_bounds__(256)
head_kernel(const float* __restrict__ pool,
            const float* __restrict__ Wf1, const float* __restrict__ bf1,
            const float* __restrict__ Wf2, const float* __restrict__ bf2,
            const float* __restrict__ Wout, const float* __restrict__ bout,
            float* __restrict__ out)
{
    __shared__ float p[128], f1[128], f2[258], red[256];
    const int g = blockIdx.x, tid = threadIdx.x;
    if (tid < 128) p[tid] = pool[(size_t)g * 128 + tid];
    __syncthreads();
    if (tid < 128) {
        float s = bf1[tid];
#pragma unroll 8
        for (int k = 0; k < 128; k++) s += p[k] * Wf1[k * 128 + tid];
        f1[tid] = lrelu(s);
    }
    __syncthreads();
    for (int j = tid; j < 258; j += 256) {
        float s = bf2[j];
#pragma unroll 8
        for (int k = 0; k < 128; k++) s += f1[k] * Wf2[k * 258 + j];
        f2[j] = lrelu(s);
    }
    __syncthreads();
    float s = 0.f;
    for (int k = tid; k < 258; k += 256) s += f2[k] * Wout[k];
    red[tid] = s;
    __syncthreads();
    for (int off = 128; off > 0; off >>= 1) {
        if (tid < off) red[tid] += red[tid + off];
        __syncthreads();
    }
    if (tid == 0) {
        float v = red[0] + bout[0];
        out[g] = 1.f / (1.f + expf(-v));
    }
}

// ---------------- launch ----------------
extern "C" void kernel_launch(void* const* d_in, const int* in_sizes, int n_in,
                              void* d_out, int out_size)
{
    const float* x      = (const float*)d_in[0];
    const int*   ei     = (const int*)  d_in[1];
    const int*   batch  = (const int*)  d_in[2];
    const float* eattr  = (const float*)d_in[3];
    const float* Wrel1  = (const float*)d_in[4];
    const float* brel1  = (const float*)d_in[5];
    const float* Wroot1 = (const float*)d_in[6];
    const float* Wrel2  = (const float*)d_in[7];
    const float* brel2  = (const float*)d_in[8];
    const float* Wroot2 = (const float*)d_in[9];
    const float* Wsig   = (const float*)d_in[10];
    const float* bsig   = (const float*)d_in[11];
    const float* Wtanh  = (const float*)d_in[12];
    const float* btanh  = (const float*)d_in[13];
    const float* Wf1    = (const float*)d_in[14];
    const float* bf1    = (const float*)d_in[15];
    const float* Wf2    = (const float*)d_in[16];
    const float* bf2    = (const float*)d_in[17];
    const float* Wout   = (const float*)d_in[18];
    const float* bout   = (const float*)d_in[19];
    float* out = (float*)d_out;

    const int* src = ei;
    const int* dst = ei + N_EDGES;

    float *agg1, *agg2, *h1, *h2, *pool;
    int *deg, *rowptr, *fill, *blksum;
    int2 *epak;
    cudaGetSymbolAddress((void**)&agg1,   g_agg1);
    cudaGetSymbolAddress((void**)&agg2,   g_agg2);
    cudaGetSymbolAddress((void**)&h1,     g_h1);
    cudaGetSymbolAddress((void**)&h2,     g_h2);
    cudaGetSymbolAddress((void**)&pool,   g_pool);
    cudaGetSymbolAddress((void**)&deg,    g_deg);
    cudaGetSymbolAddress((void**)&rowptr, g_rowptr);
    cudaGetSymbolAddress((void**)&fill,   g_fill);
    cudaGetSymbolAddress((void**)&epak,   g_epak);
    cudaGetSymbolAddress((void**)&blksum, g_blksum);

    const int mmaBlocks  = (N_NODES + 127) / 128;
    const int scanBlocks = (N_NODES + 255) / 256;
    const int edgeBlocks = (N_EDGES + 255) / 256;
    // smem: linear = (A 128 + B 128) * 2 planes; gate = (A 128 + B 256) * 2 planes
    const int SMEM_LIN  = (128 + 128) * 2 * PITCH * 2;        // 73728
    const int SMEM_GATE = (128 + 256) * 2 * PITCH * 2;        // 110592

    static int attrs_set = 0;
    if (!attrs_set) {
        cudaFuncSetAttribute(mma_linear_kernel<IN_DIM, IN_DIM>,
                             cudaFuncAttributeMaxDynamicSharedMemorySize, SMEM_LIN);
        cudaFuncSetAttribute(mma_linear_kernel<HID, HID>,
                             cudaFuncAttributeMaxDynamicSharedMemorySize, SMEM_LIN);
        cudaFuncSetAttribute(mma_gate_kernel,
                             cudaFuncAttributeMaxDynamicSharedMemorySize, SMEM_GATE);
        attrs_set = 1;
    }

    // ---- CSR build (shared by both layers) ----
    zero_int_kernel<<<scanBlocks, 256>>>(deg, N_NODES);
    hist_kernel<<<edgeBlocks, 256>>>(dst, deg);
    scan1_kernel<<<scanBlocks, 256>>>(deg, rowptr, blksum);
    scan2_kernel<<<1, 512>>>(blksum, scanBlocks);
    scan3_kernel<<<scanBlocks, 256>>>(rowptr, fill, blksum);
    fill_kernel<<<edgeBlocks, 256>>>(src, dst, eattr, fill, epak);

    // ---- layer 1 ----
    gather_kernel<IN_DIM><<<(N_NODES * 32 + 255) / 256, 256>>>(x, rowptr, deg, epak, agg1);
    mma_linear_kernel<IN_DIM, IN_DIM><<<mmaBlocks, 256, SMEM_LIN>>>(agg1, x, Wrel1, Wroot1, brel1, h1);
    // ---- layer 2 ----
    gather_kernel<HID><<<(N_NODES * 32 + 255) / 256, 256>>>(h1, rowptr, deg, epak, agg2);
    mma_linear_kernel<HID, HID><<<mmaBlocks, 256, SMEM_LIN>>>(agg2, h1, Wrel2, Wroot2, brel2, h2);
    // ---- gate + pool ----
    {
        int n4 = N_GRAPHS * HID / 4;
        zero_f4_kernel<<<(n4 + 255) / 256, 256>>>((float4*)pool, n4);
        mma_gate_kernel<<<mmaBlocks, 256, SMEM_GATE>>>(h2, x, Wsig, Wtanh, bsig, btanh, batch, pool);
    }
    // ---- head ----
    head_kernel<<<N_GRAPHS, 256>>>(pool, Wf1, bf1, Wf2, bf2, Wout, bout, out);
}